// round 13
// baseline (speedup 1.0000x reference)
#include <cuda_runtime.h>
#include <cstdint>

// SSIM loss, fully fused — horizontal-first separable blur, f32x2 row-pair packing,
// LDS.128 interleaved smem, cp.async triple-buffered pipeline.
// Round 13: prefetch issued MID-compute (off the barrier-critical path); CP_WAIT(0)
// at chunk start (a full chunk after issue). Joint single-divide SSIM in fast path.

#define IMG_H 1024
#define IMG_W 1024
#define W_OUT 118
#define EW    128          // blockDim.x
#define ROWS  205          // 5 * 205 = 1025 >= 1024 (tail guarded)
#define GRID_Y 5
#define CHUNK 12
#define NCHUNKS ((ROWS + CHUNK - 1) / CHUNK)      // 18
#define NBLK  (9 * GRID_Y * 16)                   // 720

typedef unsigned long long u64;

__device__ double g_acc = 0.0;
__device__ unsigned int g_cnt = 0u;

__device__ __forceinline__ u64 fma2(u64 a, u64 b, u64 c) {
    u64 d; asm("fma.rn.f32x2 %0, %1, %2, %3;" : "=l"(d) : "l"(a), "l"(b), "l"(c)); return d;
}
__device__ __forceinline__ u64 mul2(u64 a, u64 b) {
    u64 d; asm("mul.rn.f32x2 %0, %1, %2;" : "=l"(d) : "l"(a), "l"(b)); return d;
}
__device__ __forceinline__ u64 add2(u64 a, u64 b) {
    u64 d; asm("add.rn.f32x2 %0, %1, %2;" : "=l"(d) : "l"(a), "l"(b)); return d;
}
__device__ __forceinline__ u64 sub2(u64 a, u64 b) {
    u64 d; asm("sub.rn.f32x2 %0, %1, %2;" : "=l"(d) : "l"(a), "l"(b)); return d;
}
__device__ __forceinline__ u64 pack2(float lo, float hi) {
    u64 d; asm("mov.b64 %0, {%1, %2};" : "=l"(d) : "f"(lo), "f"(hi)); return d;
}
__device__ __forceinline__ void unpack2(u64 v, float& lo, float& hi) {
    asm("mov.b64 {%0, %1}, %2;" : "=f"(lo), "=f"(hi) : "l"(v));
}
__device__ __forceinline__ void cpa4(uint32_t dst, const float* src, unsigned sz) {
    asm volatile("cp.async.ca.shared.global [%0], [%1], 4, %2;"
                 :: "r"(dst), "l"(src), "r"(sz));
}
#define CP_COMMIT() asm volatile("cp.async.commit_group;" ::: "memory")
#define CP_WAIT(n)  asm volatile("cp.async.wait_group %0;" :: "n"(n) : "memory")

// -------- per-pair compute macro; GUARD is a 0/1 literal, folded at compile time ------
#define PAIR_COMPUTE(SLOT, J, GUARD) do {                                           \
  if (!(GUARD) || (rb + 2 * (J) < ROWS)) {                                          \
    u64 h1 = 0, h2 = 0, h3a = 0, h3b = 0, h5 = 0;                                   \
    _Pragma("unroll")                                                               \
    for (int k = 0; k < 11; ++k) {                                                  \
      const float4 t4 = sab4[SLOT][J][tid - 5 + k];                                 \
      const u64 A = *(const u64*)&t4.x;                                             \
      const u64 B = *(const u64*)&t4.z;                                             \
      const u64 w = KW2(k);                                                         \
      const u64 ta = mul2(w, A);                                                    \
      const u64 tb = mul2(w, B);                                                    \
      h1 = add2(h1, ta);                                                            \
      h2 = add2(h2, tb);                                                            \
      h3a = fma2(ta, A, h3a);                                                       \
      h3b = fma2(tb, B, h3b);                                                       \
      h5 = fma2(ta, B, h5);                                                         \
    }                                                                               \
    const u64 h3 = add2(h3a, h3b);                                                  \
    unpack2(h1, v1[(2*(J)+10)%12], v1[(2*(J)+11)%12]);                              \
    unpack2(h2, v2[(2*(J)+10)%12], v2[(2*(J)+11)%12]);                              \
    unpack2(h3, v3[(2*(J)+10)%12], v3[(2*(J)+11)%12]);                              \
    unpack2(h5, v5[(2*(J)+10)%12], v5[(2*(J)+11)%12]);                              \
    float m1q0, m2q0, m3q0, m5q0, m1q1, m2q1, m3q1, m5q1;                           \
    { float m1=0.f, m2=0.f, m3=0.f, m5=0.f;                                         \
      _Pragma("unroll")                                                             \
      for (int d = 0; d < 11; ++d) {                                                \
        const int s = (2*(J) + d) % 12;                                             \
        m1 = fmaf(KW[d], v1[s], m1); m2 = fmaf(KW[d], v2[s], m2);                   \
        m3 = fmaf(KW[d], v3[s], m3); m5 = fmaf(KW[d], v5[s], m5); }                 \
      m1q0=m1; m2q0=m2; m3q0=m3; m5q0=m5; }                                         \
    { float m1=0.f, m2=0.f, m3=0.f, m5=0.f;                                         \
      _Pragma("unroll")                                                             \
      for (int d = 0; d < 11; ++d) {                                                \
        const int s = (2*(J) + 1 + d) % 12;                                         \
        m1 = fmaf(KW[d], v1[s], m1); m2 = fmaf(KW[d], v2[s], m2);                   \
        m3 = fmaf(KW[d], v3[s], m3); m5 = fmaf(KW[d], v5[s], m5); }                 \
      m1q1=m1; m2q1=m2; m3q1=m3; m5q1=m5; }                                         \
    const u64 M1 = pack2(m1q0, m1q1), M2 = pack2(m2q0, m2q1);                       \
    const u64 M3 = pack2(m3q0, m3q1), M5 = pack2(m5q0, m5q1);                       \
    const u64 MU12 = mul2(M1, M2);                                                  \
    const u64 T    = add2(mul2(M1, M1), mul2(M2, M2));                              \
    const u64 NUM  = mul2(fma2(TW2, MU12, C1V), fma2(TW2, sub2(M5, MU12), C2V));    \
    const u64 DEN  = mul2(add2(T, C1V), add2(sub2(M3, T), C2V));                    \
    float n0, n1, d0, d1; unpack2(NUM, n0, n1); unpack2(DEN, d0, d1);               \
    if (!(GUARD)) {                                                                 \
      const float s = fmaf(n0, d1, n1 * d0);                                        \
      acc += __fdividef(s, d0 * d1);                                                \
    } else {                                                                        \
      if (y0 + rb + 2*(J)     < IMG_H) acc += __fdividef(n0, d0);                   \
      if (y0 + rb + 2*(J) + 1 < IMG_H) acc += __fdividef(n1, d1);                   \
    }                                                                               \
  } } while (0)

// prefetch chunk NC (rb2 = NC*CHUNK) — executed by ALL threads (not hok-gated)
#define PREFETCH_CHUNK(C) do {                                                      \
  if ((C) + 1 < NCHUNKS) {                                                          \
    const int rb2 = ((C) + 1) * CHUNK;                                              \
    const uint32_t dbase = sbt + (uint32_t)(((C) + 1) % 3) * 12288u;                \
    if (y0 + rb2 + 16 < IMG_H) {                                                    \
      _Pragma("unroll")                                                             \
      for (int j = 0; j < 6; ++j) {                                                 \
        const uint32_t d = dbase + (uint32_t)j * 2048u;                             \
        cpa4(d,        q1 + j * 2048,        sz4);                                  \
        cpa4(d + 4u,   q1 + j * 2048 + 1024, sz4);                                  \
        cpa4(d + 8u,   q2 + j * 2048,        sz4);                                  \
        cpa4(d + 12u,  q2 + j * 2048 + 1024, sz4);                                  \
      }                                                                             \
    } else {                                                                        \
      _Pragma("unroll")                                                             \
      for (int j = 0; j < 6; ++j) {                                                 \
        if (rb2 + 2 * j < ROWS) {                                                   \
          const int r0 = y0 + rb2 + 5 + 2 * j, r1 = r0 + 1;                         \
          const uint32_t d = dbase + (uint32_t)j * 2048u;                           \
          cpa4(d,        p1 + (size_t)r0 * IMG_W, (xok && r0 < IMG_H) ? 4u : 0u);   \
          cpa4(d + 4u,   p1 + (size_t)r1 * IMG_W, (xok && r1 < IMG_H) ? 4u : 0u);   \
          cpa4(d + 8u,   p2 + (size_t)r0 * IMG_W, (xok && r0 < IMG_H) ? 4u : 0u);   \
          cpa4(d + 12u,  p2 + (size_t)r1 * IMG_W, (xok && r1 < IMG_H) ? 4u : 0u);   \
        }                                                                           \
      }                                                                             \
    }                                                                               \
    CP_COMMIT();                                                                    \
  }                                                                                 \
  q1 += CHUNK * IMG_W;                                                              \
  q2 += CHUNK * IMG_W;                                                              \
} while (0)

__global__ __launch_bounds__(EW, 5) void ssim_kernel(const float* __restrict__ img1,
                                                     const float* __restrict__ img2,
                                                     float* __restrict__ out) {
    const float KW[11] = {
        0.0010283853f, 0.0075987626f, 0.0360007730f, 0.1093606900f,
        0.2130055300f, 0.2660117200f, 0.2130055300f, 0.1093606900f,
        0.0360007730f, 0.0075987626f, 0.0010283853f
    };
    u64 kw2[6];   // symmetric kernel: 6 distinct packed weights
    #pragma unroll
    for (int k = 0; k < 6; ++k) kw2[k] = pack2(KW[k], KW[k]);
#define KW2(k) kw2[(k) < 6 ? (k) : 10 - (k)]

    const unsigned c1b = __float_as_uint(0.0001f);
    const unsigned c2b = __float_as_uint(0.0009f);
    const unsigned twb = __float_as_uint(2.0f);
    const u64 C1V = ((u64)c1b << 32) | c1b;
    const u64 C2V = ((u64)c2b << 32) | c2b;
    const u64 TW2 = ((u64)twb << 32) | twb;

    const int tid = threadIdx.x;
    const size_t base = (size_t)blockIdx.z * (size_t)(IMG_H * IMG_W);
    const int xg  = blockIdx.x * W_OUT - 5 + tid;
    const bool xok = (xg >= 0) && (xg < IMG_W);
    const unsigned sz4 = xok ? 4u : 0u;
    const int y0  = blockIdx.y * ROWS;
    const float* p1 = img1 + base + xg;
    const float* p2 = img2 + base + xg;

    __shared__ float4 sab4[3][6][EW];   // interleaved {a_r0,a_r1,b_r0,b_r1}: 36 KB
    __shared__ float red[4];

    uint32_t sb;
    asm("{ .reg .u64 t; cvta.to.shared.u64 t, %1; cvt.u32.u64 %0, t; }"
        : "=r"(sb) : "l"((void*)&sab4[0][0][0]));
    const uint32_t sbt = sb + (uint32_t)tid * 16u;

    float v1[12], v2[12], v3[12], v5[12];   // rings: mu1, mu2, ss, ab
    const bool hok = (tid >= 5) && (tid < 5 + W_OUT) && (xg < IMG_W);
    float acc = 0.f;

    // ---------- issue prime (5 pairs -> slot 2) and chunk 0 (6 pairs -> slot 0) ----------
    #pragma unroll
    for (int i = 0; i < 5; ++i) {
        const int r0 = y0 - 5 + 2 * i, r1 = r0 + 1;
        const uint32_t d = sbt + 2u * 12288u + (uint32_t)i * 2048u;
        cpa4(d,        p1 + (size_t)r0 * IMG_W, (xok && r0 >= 0) ? 4u : 0u);
        cpa4(d + 4u,   p1 + (size_t)r1 * IMG_W, (xok && r1 >= 0) ? 4u : 0u);
        cpa4(d + 8u,   p2 + (size_t)r0 * IMG_W, (xok && r0 >= 0) ? 4u : 0u);
        cpa4(d + 12u,  p2 + (size_t)r1 * IMG_W, (xok && r1 >= 0) ? 4u : 0u);
    }
    CP_COMMIT();
    #pragma unroll
    for (int j = 0; j < 6; ++j) {
        const int r0 = y0 + 5 + 2 * j, r1 = r0 + 1;
        const uint32_t d = sbt + (uint32_t)j * 2048u;
        cpa4(d,        p1 + (size_t)r0 * IMG_W, (xok && r0 < IMG_H) ? 4u : 0u);
        cpa4(d + 4u,   p1 + (size_t)r1 * IMG_W, (xok && r1 < IMG_H) ? 4u : 0u);
        cpa4(d + 8u,   p2 + (size_t)r0 * IMG_W, (xok && r0 < IMG_H) ? 4u : 0u);
        cpa4(d + 12u,  p2 + (size_t)r1 * IMG_W, (xok && r1 < IMG_H) ? 4u : 0u);
    }
    CP_COMMIT();
    CP_WAIT(1);            // prime complete; chunk 0 still in flight
    __syncthreads();

    // ---------- prime horizontal: 5 pairs (slot 2) -> ring elements 0..9 ----------
    if (hok) {
        #pragma unroll
        for (int i = 0; i < 5; ++i) {
            u64 h1 = 0, h2 = 0, h3a = 0, h3b = 0, h5 = 0;
            #pragma unroll
            for (int k = 0; k < 11; ++k) {
                const float4 t4 = sab4[2][i][tid - 5 + k];
                const u64 A = *(const u64*)&t4.x;
                const u64 B = *(const u64*)&t4.z;
                const u64 w = KW2(k);
                const u64 ta = mul2(w, A);
                const u64 tb = mul2(w, B);
                h1 = add2(h1, ta);
                h2 = add2(h2, tb);
                h3a = fma2(ta, A, h3a);
                h3b = fma2(tb, B, h3b);
                h5 = fma2(ta, B, h5);
            }
            const u64 h3 = add2(h3a, h3b);
            unpack2(h1, v1[2*i], v1[2*i+1]);
            unpack2(h2, v2[2*i], v2[2*i+1]);
            unpack2(h3, v3[2*i], v3[2*i+1]);
            unpack2(h5, v5[2*i], v5[2*i+1]);
        }
    }
    v1[10] = v2[10] = v3[10] = v5[10] = 0.f;
    v1[11] = v2[11] = v3[11] = v5[11] = 0.f;

    // prefetch pointers: chunk 1's first row = y0 + CHUNK + 5
    const float* q1 = p1 + (size_t)(y0 + CHUNK + 5) * IMG_W;
    const float* q2 = p2 + (size_t)(y0 + CHUNK + 5) * IMG_W;

    // ---------- main loop: wait(0) -> barrier -> pair0 -> prefetch(c+1) -> pairs1-5 ----------
    for (int c = 0; c < NCHUNKS; ++c) {
        const int rb = c * CHUNK;
        const int slot = c % 3;

        CP_WAIT(0);        // chunk c's group — issued a full chunk ago, already landed
        __syncthreads();

        const bool fast = (rb + 11 < ROWS) && (y0 + rb + 11 < IMG_H);
        if (fast) {
            if (hok) { PAIR_COMPUTE(slot, 0, 0); }
            PREFETCH_CHUNK(c);                         // off the barrier path
            if (hok) {
                PAIR_COMPUTE(slot, 1, 0);
                PAIR_COMPUTE(slot, 2, 0);
                PAIR_COMPUTE(slot, 3, 0);
                PAIR_COMPUTE(slot, 4, 0);
                PAIR_COMPUTE(slot, 5, 0);
            }
        } else {
            PREFETCH_CHUNK(c);
            if (hok) {
                PAIR_COMPUTE(slot, 0, 1);
                PAIR_COMPUTE(slot, 1, 1);
                PAIR_COMPUTE(slot, 2, 1);
                PAIR_COMPUTE(slot, 3, 1);
                PAIR_COMPUTE(slot, 4, 1);
                PAIR_COMPUTE(slot, 5, 1);
            }
        }
    }

    // ---------- reduction + last-block finalize ----------
    #pragma unroll
    for (int o = 16; o; o >>= 1) acc += __shfl_xor_sync(0xffffffffu, acc, o);
    if ((tid & 31) == 0) red[tid >> 5] = acc;
    __syncthreads();
    if (tid == 0) {
        const double t = (double)(red[0] + red[1] + red[2] + red[3]);
        atomicAdd(&g_acc, t);
        __threadfence();
        const unsigned int n = atomicAdd(&g_cnt, 1u);
        if (n == NBLK - 1) {
            const double total = atomicAdd(&g_acc, 0.0);
            out[0] = (float)(1.0 - total / 16777216.0);
            atomicExch((unsigned long long*)&g_acc, 0ull);
            atomicExch(&g_cnt, 0u);
        }
    }
}

extern "C" void kernel_launch(void* const* d_in, const int* in_sizes, int n_in,
                              void* d_out, int out_size) {
    const float* img1 = (const float*)d_in[0];
    const float* img2 = (const float*)d_in[1];
    float* out = (float*)d_out;

    dim3 grid((IMG_W + W_OUT - 1) / W_OUT, GRID_Y, 16);  // (9, 5, 16) = 720 CTAs
    ssim_kernel<<<grid, EW>>>(img1, img2, out);
}

// round 14
// speedup vs baseline: 1.0336x; 1.0336x over previous
#include <cuda_runtime.h>
#include <cstdint>

// SSIM loss, fully fused — horizontal-first separable blur, f32x2 row-pair packing,
// LDS.128 interleaved smem {a_r0,a_r1,b_r0,b_r1}, cp.async triple-buffered pipeline
// (round-12 structure: prefetch at chunk top, CP_WAIT(1), one barrier per chunk).
// Round 14: k=0 accumulator init (no zero-adds through inline asm) + joint single
// divide in the fast path.

#define IMG_H 1024
#define IMG_W 1024
#define W_OUT 118
#define EW    128          // blockDim.x
#define ROWS  205          // 5 * 205 = 1025 >= 1024 (tail guarded)
#define GRID_Y 5
#define CHUNK 12
#define NCHUNKS ((ROWS + CHUNK - 1) / CHUNK)      // 18
#define NBLK  (9 * GRID_Y * 16)                   // 720

typedef unsigned long long u64;

__device__ double g_acc = 0.0;
__device__ unsigned int g_cnt = 0u;

__device__ __forceinline__ u64 fma2(u64 a, u64 b, u64 c) {
    u64 d; asm("fma.rn.f32x2 %0, %1, %2, %3;" : "=l"(d) : "l"(a), "l"(b), "l"(c)); return d;
}
__device__ __forceinline__ u64 mul2(u64 a, u64 b) {
    u64 d; asm("mul.rn.f32x2 %0, %1, %2;" : "=l"(d) : "l"(a), "l"(b)); return d;
}
__device__ __forceinline__ u64 add2(u64 a, u64 b) {
    u64 d; asm("add.rn.f32x2 %0, %1, %2;" : "=l"(d) : "l"(a), "l"(b)); return d;
}
__device__ __forceinline__ u64 sub2(u64 a, u64 b) {
    u64 d; asm("sub.rn.f32x2 %0, %1, %2;" : "=l"(d) : "l"(a), "l"(b)); return d;
}
__device__ __forceinline__ u64 pack2(float lo, float hi) {
    u64 d; asm("mov.b64 %0, {%1, %2};" : "=l"(d) : "f"(lo), "f"(hi)); return d;
}
__device__ __forceinline__ void unpack2(u64 v, float& lo, float& hi) {
    asm("mov.b64 {%0, %1}, %2;" : "=f"(lo), "=f"(hi) : "l"(v));
}
__device__ __forceinline__ void cpa4(uint32_t dst, const float* src, unsigned sz) {
    asm volatile("cp.async.ca.shared.global [%0], [%1], 4, %2;"
                 :: "r"(dst), "l"(src), "r"(sz));
}
#define CP_COMMIT() asm volatile("cp.async.commit_group;" ::: "memory")
#define CP_WAIT(n)  asm volatile("cp.async.wait_group %0;" :: "n"(n) : "memory")

// -------- per-pair compute macro; GUARD is a 0/1 literal, folded at compile time ------
#define PAIR_COMPUTE(SLOT, J, GUARD) do {                                           \
  if (!(GUARD) || (rb + 2 * (J) < ROWS)) {                                          \
    u64 h1, h2, h3a, h3b, h5;                                                       \
    { /* k = 0: initialize accumulators directly (no zero-adds) */                  \
      const float4 t4 = sab4[SLOT][J][tid - 5];                                     \
      const u64 A = *(const u64*)&t4.x;                                             \
      const u64 B = *(const u64*)&t4.z;                                             \
      const u64 w = KW2(0);                                                         \
      const u64 ta = mul2(w, A);                                                    \
      const u64 tb = mul2(w, B);                                                    \
      h1 = ta; h2 = tb;                                                             \
      h3a = mul2(ta, A); h3b = mul2(tb, B); h5 = mul2(ta, B);                       \
    }                                                                               \
    _Pragma("unroll")                                                               \
    for (int k = 1; k < 11; ++k) {                                                  \
      const float4 t4 = sab4[SLOT][J][tid - 5 + k];                                 \
      const u64 A = *(const u64*)&t4.x;                                             \
      const u64 B = *(const u64*)&t4.z;                                             \
      const u64 w = KW2(k);                                                         \
      const u64 ta = mul2(w, A);                                                    \
      const u64 tb = mul2(w, B);                                                    \
      h1 = add2(h1, ta);                                                            \
      h2 = add2(h2, tb);                                                            \
      h3a = fma2(ta, A, h3a);                                                       \
      h3b = fma2(tb, B, h3b);                                                       \
      h5 = fma2(ta, B, h5);                                                         \
    }                                                                               \
    const u64 h3 = add2(h3a, h3b);                                                  \
    unpack2(h1, v1[(2*(J)+10)%12], v1[(2*(J)+11)%12]);                              \
    unpack2(h2, v2[(2*(J)+10)%12], v2[(2*(J)+11)%12]);                              \
    unpack2(h3, v3[(2*(J)+10)%12], v3[(2*(J)+11)%12]);                              \
    unpack2(h5, v5[(2*(J)+10)%12], v5[(2*(J)+11)%12]);                              \
    float m1q0, m2q0, m3q0, m5q0, m1q1, m2q1, m3q1, m5q1;                           \
    { float m1=0.f, m2=0.f, m3=0.f, m5=0.f;                                         \
      _Pragma("unroll")                                                             \
      for (int d = 0; d < 11; ++d) {                                                \
        const int s = (2*(J) + d) % 12;                                             \
        m1 = fmaf(KW[d], v1[s], m1); m2 = fmaf(KW[d], v2[s], m2);                   \
        m3 = fmaf(KW[d], v3[s], m3); m5 = fmaf(KW[d], v5[s], m5); }                 \
      m1q0=m1; m2q0=m2; m3q0=m3; m5q0=m5; }                                         \
    { float m1=0.f, m2=0.f, m3=0.f, m5=0.f;                                         \
      _Pragma("unroll")                                                             \
      for (int d = 0; d < 11; ++d) {                                                \
        const int s = (2*(J) + 1 + d) % 12;                                         \
        m1 = fmaf(KW[d], v1[s], m1); m2 = fmaf(KW[d], v2[s], m2);                   \
        m3 = fmaf(KW[d], v3[s], m3); m5 = fmaf(KW[d], v5[s], m5); }                 \
      m1q1=m1; m2q1=m2; m3q1=m3; m5q1=m5; }                                         \
    const u64 M1 = pack2(m1q0, m1q1), M2 = pack2(m2q0, m2q1);                       \
    const u64 M3 = pack2(m3q0, m3q1), M5 = pack2(m5q0, m5q1);                       \
    const u64 MU12 = mul2(M1, M2);                                                  \
    const u64 T    = add2(mul2(M1, M1), mul2(M2, M2));                              \
    const u64 NUM  = mul2(fma2(TW2, MU12, C1V), fma2(TW2, sub2(M5, MU12), C2V));    \
    const u64 DEN  = mul2(add2(T, C1V), add2(sub2(M3, T), C2V));                    \
    float n0, n1, d0, d1; unpack2(NUM, n0, n1); unpack2(DEN, d0, d1);               \
    if (!(GUARD)) {                                                                 \
      acc += __fdividef(fmaf(n0, d1, n1 * d0), d0 * d1);                            \
    } else {                                                                        \
      if (y0 + rb + 2*(J)     < IMG_H) acc += __fdividef(n0, d0);                   \
      if (y0 + rb + 2*(J) + 1 < IMG_H) acc += __fdividef(n1, d1);                   \
    }                                                                               \
  } } while (0)

__global__ __launch_bounds__(EW, 5) void ssim_kernel(const float* __restrict__ img1,
                                                     const float* __restrict__ img2,
                                                     float* __restrict__ out) {
    const float KW[11] = {
        0.0010283853f, 0.0075987626f, 0.0360007730f, 0.1093606900f,
        0.2130055300f, 0.2660117200f, 0.2130055300f, 0.1093606900f,
        0.0360007730f, 0.0075987626f, 0.0010283853f
    };
    u64 kw2[6];   // symmetric kernel: 6 distinct packed weights
    #pragma unroll
    for (int k = 0; k < 6; ++k) kw2[k] = pack2(KW[k], KW[k]);
#define KW2(k) kw2[(k) < 6 ? (k) : 10 - (k)]

    const unsigned c1b = __float_as_uint(0.0001f);
    const unsigned c2b = __float_as_uint(0.0009f);
    const unsigned twb = __float_as_uint(2.0f);
    const u64 C1V = ((u64)c1b << 32) | c1b;
    const u64 C2V = ((u64)c2b << 32) | c2b;
    const u64 TW2 = ((u64)twb << 32) | twb;

    const int tid = threadIdx.x;
    const size_t base = (size_t)blockIdx.z * (size_t)(IMG_H * IMG_W);
    const int xg  = blockIdx.x * W_OUT - 5 + tid;
    const bool xok = (xg >= 0) && (xg < IMG_W);
    const unsigned sz4 = xok ? 4u : 0u;
    const int y0  = blockIdx.y * ROWS;
    const float* p1 = img1 + base + xg;
    const float* p2 = img2 + base + xg;

    __shared__ float4 sab4[3][6][EW];   // interleaved {a_r0,a_r1,b_r0,b_r1}: 36 KB
    __shared__ float red[4];

    uint32_t sb;
    asm("{ .reg .u64 t; cvta.to.shared.u64 t, %1; cvt.u32.u64 %0, t; }"
        : "=r"(sb) : "l"((void*)&sab4[0][0][0]));
    const uint32_t sbt = sb + (uint32_t)tid * 16u;

    float v1[12], v2[12], v3[12], v5[12];   // rings: mu1, mu2, ss, ab
    const bool hok = (tid >= 5) && (tid < 5 + W_OUT) && (xg < IMG_W);
    float acc = 0.f;

    // ---------- issue prime (5 pairs -> slot 2) and chunk 0 (6 pairs -> slot 0) ----------
    #pragma unroll
    for (int i = 0; i < 5; ++i) {
        const int r0 = y0 - 5 + 2 * i, r1 = r0 + 1;
        const uint32_t d = sbt + 2u * 12288u + (uint32_t)i * 2048u;
        cpa4(d,        p1 + (size_t)r0 * IMG_W, (xok && r0 >= 0) ? 4u : 0u);
        cpa4(d + 4u,   p1 + (size_t)r1 * IMG_W, (xok && r1 >= 0) ? 4u : 0u);
        cpa4(d + 8u,   p2 + (size_t)r0 * IMG_W, (xok && r0 >= 0) ? 4u : 0u);
        cpa4(d + 12u,  p2 + (size_t)r1 * IMG_W, (xok && r1 >= 0) ? 4u : 0u);
    }
    CP_COMMIT();
    #pragma unroll
    for (int j = 0; j < 6; ++j) {
        const int r0 = y0 + 5 + 2 * j, r1 = r0 + 1;
        const uint32_t d = sbt + (uint32_t)j * 2048u;
        cpa4(d,        p1 + (size_t)r0 * IMG_W, (xok && r0 < IMG_H) ? 4u : 0u);
        cpa4(d + 4u,   p1 + (size_t)r1 * IMG_W, (xok && r1 < IMG_H) ? 4u : 0u);
        cpa4(d + 8u,   p2 + (size_t)r0 * IMG_W, (xok && r0 < IMG_H) ? 4u : 0u);
        cpa4(d + 12u,  p2 + (size_t)r1 * IMG_W, (xok && r1 < IMG_H) ? 4u : 0u);
    }
    CP_COMMIT();
    CP_WAIT(1);
    __syncthreads();

    // ---------- prime horizontal: 5 pairs (slot 2) -> ring elements 0..9 ----------
    if (hok) {
        #pragma unroll
        for (int i = 0; i < 5; ++i) {
            u64 h1, h2, h3a, h3b, h5;
            {
                const float4 t4 = sab4[2][i][tid - 5];
                const u64 A = *(const u64*)&t4.x;
                const u64 B = *(const u64*)&t4.z;
                const u64 w = KW2(0);
                const u64 ta = mul2(w, A);
                const u64 tb = mul2(w, B);
                h1 = ta; h2 = tb;
                h3a = mul2(ta, A); h3b = mul2(tb, B); h5 = mul2(ta, B);
            }
            #pragma unroll
            for (int k = 1; k < 11; ++k) {
                const float4 t4 = sab4[2][i][tid - 5 + k];
                const u64 A = *(const u64*)&t4.x;
                const u64 B = *(const u64*)&t4.z;
                const u64 w = KW2(k);
                const u64 ta = mul2(w, A);
                const u64 tb = mul2(w, B);
                h1 = add2(h1, ta);
                h2 = add2(h2, tb);
                h3a = fma2(ta, A, h3a);
                h3b = fma2(tb, B, h3b);
                h5 = fma2(ta, B, h5);
            }
            const u64 h3 = add2(h3a, h3b);
            unpack2(h1, v1[2*i], v1[2*i+1]);
            unpack2(h2, v2[2*i], v2[2*i+1]);
            unpack2(h3, v3[2*i], v3[2*i+1]);
            unpack2(h5, v5[2*i], v5[2*i+1]);
        }
    }
    v1[10] = v2[10] = v3[10] = v5[10] = 0.f;
    v1[11] = v2[11] = v3[11] = v5[11] = 0.f;

    // incrementally advanced prefetch pointers (chunk 1 rows start at y0+17)
    const float* q1 = p1 + (size_t)(y0 + CHUNK + 5) * IMG_W;
    const float* q2 = p2 + (size_t)(y0 + CHUNK + 5) * IMG_W;

    // ---------- main loop: 12-row chunks, one barrier each (round-12 structure) ----------
    for (int c = 0; c < NCHUNKS; ++c) {
        const int rb = c * CHUNK;
        const int slot = c % 3;

        if (c + 1 < NCHUNKS) {
            const int rb2 = rb + CHUNK;
            const uint32_t dbase = sbt + (uint32_t)((c + 1) % 3) * 12288u;
            if (y0 + rb2 + 16 < IMG_H) {
                // fast path: all rows in-bounds (extra pairs beyond ROWS harmless)
                #pragma unroll
                for (int j = 0; j < 6; ++j) {
                    const uint32_t d = dbase + (uint32_t)j * 2048u;
                    cpa4(d,        q1 + j * 2048,        sz4);
                    cpa4(d + 4u,   q1 + j * 2048 + 1024, sz4);
                    cpa4(d + 8u,   q2 + j * 2048,        sz4);
                    cpa4(d + 12u,  q2 + j * 2048 + 1024, sz4);
                }
            } else {
                #pragma unroll
                for (int j = 0; j < 6; ++j) {
                    if (rb2 + 2 * j < ROWS) {
                        const int r0 = y0 + rb2 + 5 + 2 * j, r1 = r0 + 1;
                        const uint32_t d = dbase + (uint32_t)j * 2048u;
                        cpa4(d,        p1 + (size_t)r0 * IMG_W, (xok && r0 < IMG_H) ? 4u : 0u);
                        cpa4(d + 4u,   p1 + (size_t)r1 * IMG_W, (xok && r1 < IMG_H) ? 4u : 0u);
                        cpa4(d + 8u,   p2 + (size_t)r0 * IMG_W, (xok && r0 < IMG_H) ? 4u : 0u);
                        cpa4(d + 12u,  p2 + (size_t)r1 * IMG_W, (xok && r1 < IMG_H) ? 4u : 0u);
                    }
                }
            }
            CP_COMMIT();
            CP_WAIT(1);
        } else {
            CP_WAIT(0);
        }
        q1 += CHUNK * IMG_W;
        q2 += CHUNK * IMG_W;
        __syncthreads();

        if (hok) {
            if ((rb + 11 < ROWS) && (y0 + rb + 11 < IMG_H)) {
                #pragma unroll
                for (int j = 0; j < 6; ++j) { PAIR_COMPUTE(slot, j, 0); }
            } else {
                #pragma unroll
                for (int j = 0; j < 6; ++j) { PAIR_COMPUTE(slot, j, 1); }
            }
        }
    }

    // ---------- reduction + last-block finalize ----------
    #pragma unroll
    for (int o = 16; o; o >>= 1) acc += __shfl_xor_sync(0xffffffffu, acc, o);
    if ((tid & 31) == 0) red[tid >> 5] = acc;
    __syncthreads();
    if (tid == 0) {
        const double t = (double)(red[0] + red[1] + red[2] + red[3]);
        atomicAdd(&g_acc, t);
        __threadfence();
        const unsigned int n = atomicAdd(&g_cnt, 1u);
        if (n == NBLK - 1) {
            const double total = atomicAdd(&g_acc, 0.0);
            out[0] = (float)(1.0 - total / 16777216.0);
            atomicExch((unsigned long long*)&g_acc, 0ull);
            atomicExch(&g_cnt, 0u);
        }
    }
}

extern "C" void kernel_launch(void* const* d_in, const int* in_sizes, int n_in,
                              void* d_out, int out_size) {
    const float* img1 = (const float*)d_in[0];
    const float* img2 = (const float*)d_in[1];
    float* out = (float*)d_out;

    dim3 grid((IMG_W + W_OUT - 1) / W_OUT, GRID_Y, 16);  // (9, 5, 16) = 720 CTAs
    ssim_kernel<<<grid, EW>>>(img1, img2, out);
}